// round 14
// baseline (speedup 1.0000x reference)
#include <cuda_runtime.h>
#include <cuda_bf16.h>
#include <stdint.h>

#define D_DIM 256
#define NROWS 8192
#define KCODES 8192
#define NTILES 64        // KCODES / 128 column tiles
#define CAP 96
#define MARGIN 2e-4f
#define LOSS_BLOCKS 1024

// ---------------- device scratch (no allocations allowed) ----------------
__device__ float g_x2[NROWS];
__device__ float g_c2[KCODES];
__device__ unsigned long long g_part[NROWS * NTILES];
__device__ double g_loss_part[LOSS_BLOCKS];
__device__ __nv_bfloat16 g_ab[NROWS * D_DIM];   // z_e rounded to bf16
__device__ __nv_bfloat16 g_bb[KCODES * D_DIM];  // codebook rounded to bf16
__device__ int g_ccnt[NROWS];
__device__ unsigned long long g_cand[NROWS * CAP];

// ------------------------------ helpers ----------------------------------
__device__ __forceinline__ uint32_t smem_u32(const void* p) {
    uint32_t a;
    asm("{ .reg .u64 t; cvta.to.shared.u64 t, %1; cvt.u32.u64 %0, t; }"
        : "=r"(a) : "l"(p));
    return a;
}
__device__ __forceinline__ void cpa16(uint32_t d, const void* s) {
    asm volatile("cp.async.cg.shared.global [%0], [%1], 16;"
                 :: "r"(d), "l"(s) : "memory");
}
__device__ __forceinline__ void ldsm4(uint32_t* r, uint32_t a) {
    asm volatile("ldmatrix.sync.aligned.m8n8.x4.shared.b16 {%0,%1,%2,%3}, [%4];"
                 : "=r"(r[0]), "=r"(r[1]), "=r"(r[2]), "=r"(r[3]) : "r"(a));
}
__device__ __forceinline__ void mma16816(float* d, const uint32_t* a,
                                         const uint32_t* b) {
    asm volatile(
        "mma.sync.aligned.m16n8k16.row.col.f32.bf16.bf16.f32 "
        "{%0,%1,%2,%3}, {%4,%5,%6,%7}, {%8,%9}, {%0,%1,%2,%3};"
        : "+f"(d[0]), "+f"(d[1]), "+f"(d[2]), "+f"(d[3])
        : "r"(a[0]), "r"(a[1]), "r"(a[2]), "r"(a[3]), "r"(b[0]), "r"(b[1]));
}
#define SW(o) ((uint32_t)(o) ^ (((uint32_t)(o) >> 3) & 0x70u))

// ------------- kernel 1: norms (exact R2 order) + bf16 copies ------------
__global__ void split_kernel(const float* __restrict__ ze,
                             const float* __restrict__ cb, int N, int K) {
    int gtid = blockIdx.x * blockDim.x + threadIdx.x;
    if (gtid < NROWS) g_ccnt[gtid] = 0;  // reset candidate counters each call
    int warp = gtid >> 5;
    int lane = threadIdx.x & 31;
    if (warp >= N + K) return;
    const float* src;
    float* dst;
    int row;
    bool is_code = (warp < K);
    if (is_code) { src = cb; dst = g_c2; row = warp; }
    else         { src = ze; dst = g_x2; row = warp - K; }
    const float* p = src + (size_t)row * D_DIM;
    float acc = 0.0f;
#pragma unroll
    for (int i = 0; i < D_DIM / 32; ++i) {
        float v = p[lane + 32 * i];
        acc = __fadd_rn(acc, __fmul_rn(v, v));
        __nv_bfloat16 h = __float2bfloat16(v);
        size_t off = (size_t)row * D_DIM + lane + 32 * i;
        if (is_code) g_bb[off] = h; else g_ab[off] = h;
    }
#pragma unroll
    for (int off = 16; off; off >>= 1)
        acc = __fadd_rn(acc, __shfl_down_sync(0xffffffffu, acc, off));
    if (lane == 0) dst[row] = acc;
}

// ------ kernel 2: bf16 mma.sync GEMM + tile-min + margin candidates ------
// grid (64, 32): each block does TWO 128x128 col-tiles with one continuous
// 8-chunk, 3-stage cp.async pipeline (tile-0 epilogue overlaps tile-1 loads).
__global__ __launch_bounds__(256, 2) void mma_phase1() {
    extern __shared__ char dsm[];  // 96KB: 3 stages x (A 16KB + B 16KB)
    __shared__ unsigned long long red[2][64][4];
    __shared__ unsigned long long s_minkey[128];
    __shared__ float s_min[128];
    __shared__ float s_c2[256];
    __shared__ float s_x2[128];

    const int tid = threadIdx.x;
    const int wid = tid >> 5, lane = tid & 31;
    const int mw = wid >> 2, nw = wid & 3;
    const int row0 = blockIdx.x * 128;
    const int colbase = blockIdx.y * 256;   // two adjacent 128-wide tiles
    const uint32_t sb = smem_u32(dsm);

    s_c2[tid] = g_c2[colbase + tid];
    if (tid < 128) s_x2[tid] = g_x2[row0 + tid];

    float acc[4][4][4];
#pragma unroll
    for (int i = 0; i < 4; ++i)
#pragma unroll
        for (int j = 0; j < 4; ++j)
#pragma unroll
            for (int c = 0; c < 4; ++c) acc[i][j][c] = 0.0f;

    // chunk ch (0..7): A k-chunk = (ch&3)*64, B tile = colbase + (ch>>2)*128
    auto issue = [&](int ch) {
        uint32_t ab = sb + (uint32_t)(ch % 3) * 32768u;
        uint32_t bb = ab + 16384u;
        const __nv_bfloat16* ga = g_ab + (size_t)row0 * D_DIM + (ch & 3) * 64;
        const __nv_bfloat16* gb = g_bb +
            (size_t)(colbase + (ch >> 2) * 128) * D_DIM + (ch & 3) * 64;
#pragma unroll
        for (int t = 0; t < 4; ++t) {
            int lin = tid + t * 256;      // 0..1023
            int r = lin >> 3, gi = lin & 7;
            uint32_t off = SW(r * 128 + gi * 16);
            cpa16(ab + off, ga + (size_t)r * D_DIM + gi * 8);
            cpa16(bb + off, gb + (size_t)r * D_DIM + gi * 8);
        }
        asm volatile("cp.async.commit_group;" ::: "memory");
    };

    // epilogue for col-tile ct (uses acc + s_c2[ct*128..], writes g_part/cand)
    auto epilogue = [&](int ct) {
        const int col0 = colbase + ct * 128;
        const float* c2t = &s_c2[ct * 128];
        unsigned long long klo[4], khi[4];
#pragma unroll
        for (int i = 0; i < 4; ++i) {
            int rlo = mw * 64 + i * 16 + (lane >> 2);
            float x2lo = s_x2[rlo], x2hi = s_x2[rlo + 8];
            float dlo = 3.4e38f, dhi = 3.4e38f;
            int ilo = 0, ihi = 0;
#pragma unroll
            for (int j = 0; j < 4; ++j) {
                int c0 = nw * 32 + j * 8 + (lane & 3) * 2;
#pragma unroll
                for (int c = 0; c < 2; ++c) {
                    float d = __fadd_rn(
                        __fsub_rn(x2lo, __fmul_rn(2.0f, acc[i][j][c])), c2t[c0 + c]);
                    if (d < dlo) { dlo = d; ilo = col0 + c0 + c; }
                    d = __fadd_rn(
                        __fsub_rn(x2hi, __fmul_rn(2.0f, acc[i][j][2 + c])), c2t[c0 + c]);
                    if (d < dhi) { dhi = d; ihi = col0 + c0 + c; }
                }
            }
            klo[i] = ((unsigned long long)__float_as_uint(dlo) << 32) | (unsigned)ilo;
            khi[i] = ((unsigned long long)__float_as_uint(dhi) << 32) | (unsigned)ihi;
        }
#pragma unroll
        for (int s = 1; s <= 2; s <<= 1)
#pragma unroll
            for (int i = 0; i < 4; ++i) {
                unsigned long long o = __shfl_xor_sync(0xffffffffu, klo[i], s);
                if (o < klo[i]) klo[i] = o;
                o = __shfl_xor_sync(0xffffffffu, khi[i], s);
                if (o < khi[i]) khi[i] = o;
            }
        if ((lane & 3) == 0)
#pragma unroll
            for (int i = 0; i < 4; ++i) {
                red[mw][i * 16 + (lane >> 2)][nw] = klo[i];
                red[mw][i * 16 + (lane >> 2) + 8][nw] = khi[i];
            }
        __syncthreads();
        if (tid < 128) {
            unsigned long long m = red[tid >> 6][tid & 63][0];
#pragma unroll
            for (int q = 1; q < 4; ++q) {
                unsigned long long k = red[tid >> 6][tid & 63][q];
                if (k < m) m = k;
            }
            g_part[(size_t)(row0 + tid) * NTILES + blockIdx.y * 2 + ct] = m;
            s_minkey[tid] = m;
            s_min[tid] = __uint_as_float((uint32_t)(m >> 32));
        }
        __syncthreads();
        // margin sweep: collect runner-ups within MARGIN of the tile min
#pragma unroll
        for (int i = 0; i < 4; ++i) {
            int rlo = mw * 64 + i * 16 + (lane >> 2);
#pragma unroll
            for (int half = 0; half < 2; ++half) {
                int rl = rlo + half * 8;
                float x2v = s_x2[rl];
                float thr = s_min[rl] + MARGIN;
                unsigned long long mk = s_minkey[rl];
#pragma unroll
                for (int j = 0; j < 4; ++j) {
                    int c0 = nw * 32 + j * 8 + (lane & 3) * 2;
#pragma unroll
                    for (int c = 0; c < 2; ++c) {
                        float d = __fadd_rn(
                            __fsub_rn(x2v, __fmul_rn(2.0f, acc[i][j][half * 2 + c])),
                            c2t[c0 + c]);
                        if (d <= thr) {
                            unsigned long long k =
                                ((unsigned long long)__float_as_uint(d) << 32) |
                                (unsigned)(col0 + c0 + c);
                            if (k != mk) {
                                int grow = row0 + rl;
                                int pos = atomicAdd(&g_ccnt[grow], 1);
                                if (pos < CAP) g_cand[(size_t)grow * CAP + pos] = k;
                            }
                        }
                    }
                }
            }
        }
        __syncthreads();  // red/s_minkey reuse safety for next tile
    };

    issue(0);
    issue(1);
    issue(2);
#pragma unroll
    for (int ch = 0; ch < 8; ++ch) {
        // safe waits: group ch is ALWAYS complete before its stage is read
        if (ch == 0)      asm volatile("cp.async.wait_group 2;" ::: "memory");
        else if (ch < 7)  asm volatile("cp.async.wait_group 1;" ::: "memory");
        else              asm volatile("cp.async.wait_group 0;" ::: "memory");
        __syncthreads();
        if (ch < 6) issue(ch + 2);  // stage (ch+2)%3 != ch%3; old reads done
        uint32_t ab = sb + (uint32_t)(ch % 3) * 32768u;
        uint32_t bb = ab + 16384u;
#pragma unroll
        for (int ks = 0; ks < 4; ++ks) {
            uint32_t afr[4][4], bfr[4][2];
#pragma unroll
            for (int i = 0; i < 4; ++i) {
                int r = mw * 64 + i * 16 + (lane & 15);
                uint32_t off = SW(r * 128 + (ks * 16 + (lane >> 4) * 8) * 2);
                ldsm4(afr[i], ab + off);
            }
#pragma unroll
            for (int j2 = 0; j2 < 2; ++j2) {
                // non-trans: smem B tile is [n][k]; fragment (n=l>>2, k=2(l%4))
                int n = nw * 32 + j2 * 16 + (lane & 7) + ((lane >> 4) & 1) * 8;
                uint32_t off = SW(n * 128 + (ks * 16 + ((lane >> 3) & 1) * 8) * 2);
                uint32_t t4[4];
                ldsm4(t4, bb + off);
                bfr[j2 * 2 + 0][0] = t4[0]; bfr[j2 * 2 + 0][1] = t4[1];
                bfr[j2 * 2 + 1][0] = t4[2]; bfr[j2 * 2 + 1][1] = t4[3];
            }
#pragma unroll
            for (int i = 0; i < 4; ++i)
#pragma unroll
                for (int j = 0; j < 4; ++j) mma16816(acc[i][j], afr[i], bfr[j]);
        }
        if (ch == 3) {
            epilogue(0);  // overlaps with in-flight chunks 4,5
#pragma unroll
            for (int i = 0; i < 4; ++i)
#pragma unroll
                for (int j = 0; j < 4; ++j)
#pragma unroll
                    for (int c = 0; c < 4; ++c) acc[i][j][c] = 0.0f;
        }
    }
    epilogue(1);
}

// -- kernel 3: global min + exact recheck + fused z_q/index/loss output --
// 8 warps = 8 rows per block; grid N/8 = 1024 blocks.
__global__ __launch_bounds__(256) void phase2_kernel(
    const float* __restrict__ ze, const float* __restrict__ cb,
    float* __restrict__ out_zq, float* __restrict__ out_idx) {
    __shared__ int s_list[8][192];
    __shared__ int s_cnt[8];
    __shared__ double sred[256];
    const int wid = threadIdx.x >> 5, lane = threadIdx.x & 31;
    const int row = blockIdx.x * 8 + wid;

    unsigned long long k1 = g_part[(size_t)row * NTILES + lane];
    unsigned long long k2 = g_part[(size_t)row * NTILES + 32 + lane];
    unsigned long long m = k1 < k2 ? k1 : k2;
#pragma unroll
    for (int s = 16; s; s >>= 1) {
        unsigned long long o = __shfl_xor_sync(0xffffffffu, m, s);
        if (o < m) m = o;
    }
    m = __shfl_sync(0xffffffffu, m, 0);
    float thr = __uint_as_float((uint32_t)(m >> 32)) + MARGIN;

    if (lane == 0) s_cnt[wid] = 0;
    __syncwarp();
    int cnt = g_ccnt[row];
    bool ovf = cnt > CAP;
    if (!ovf) {
        // tile-min keys already in registers (k1 = tiles 0..31, k2 = 32..63)
        if (__uint_as_float((uint32_t)(k1 >> 32)) <= thr) {
            int pos = atomicAdd(&s_cnt[wid], 1);
            s_list[wid][pos] = (int)(k1 & 0xffffffffu);
        }
        if (__uint_as_float((uint32_t)(k2 >> 32)) <= thr) {
            int pos = atomicAdd(&s_cnt[wid], 1);
            s_list[wid][pos] = (int)(k2 & 0xffffffffu);
        }
        for (int e = lane; e < cnt; e += 32) {
            unsigned long long k = g_cand[(size_t)row * CAP + e];
            if (__uint_as_float((uint32_t)(k >> 32)) <= thr) {
                int pos = atomicAdd(&s_cnt[wid], 1);
                s_list[wid][pos] = (int)(k & 0xffffffffu);
            }
        }
    }
    __syncwarp();
    int M = ovf ? KCODES : s_cnt[wid];

    const float* zp = ze + (size_t)row * D_DIM;
    float x2v = g_x2[row];
    unsigned long long best = ~0ull;
    for (int c = lane; c < M; c += 32) {
        int code = ovf ? c : s_list[wid][c];
        const float* cp = cb + (size_t)code * D_DIM;
        float a = 0.0f;  // exact serial fp32 chain (matches verified R2 values)
#pragma unroll 8
        for (int k = 0; k < D_DIM; ++k) a = fmaf(zp[k], cp[k], a);
        float d = __fadd_rn(__fsub_rn(x2v, __fmul_rn(2.0f, a)), g_c2[code]);
        unsigned long long key =
            ((unsigned long long)__float_as_uint(d) << 32) | (unsigned)code;
        if (key < best) best = key;
    }
#pragma unroll
    for (int s = 16; s; s >>= 1) {
        unsigned long long o = __shfl_xor_sync(0xffffffffu, best, s);
        if (o < best) best = o;
    }
    int idx = (int)(best & 0xffffffffu);   // all lanes agree after butterfly
    if (lane == 0) out_idx[row] = (float)idx;

    // fused gather: z_q_st row + loss partial (exact ops of verified gather)
    const float* cp = cb + (size_t)idx * D_DIM + lane * 8;
    const float* zq = zp + lane * 8;
    float* op = out_zq + (size_t)row * D_DIM + lane * 8;
    double s = 0.0;
#pragma unroll
    for (int e = 0; e < 8; ++e) {
        float z = zq[e], c = cp[e];
        op[e] = __fadd_rn(z, __fsub_rn(c, z));  // z + (z_q - z)
        float df = __fsub_rn(z, c);
        s += (double)__fmul_rn(df, df);
    }
    sred[threadIdx.x] = s;
    __syncthreads();
    for (int off = 128; off; off >>= 1) {
        if (threadIdx.x < off) sred[threadIdx.x] += sred[threadIdx.x + off];
        __syncthreads();
    }
    if (threadIdx.x == 0) g_loss_part[blockIdx.x] = sred[0];
}

// -------------------- kernel 4: final loss reduction ---------------------
__global__ void loss_final_kernel(float* __restrict__ out_loss,
                                  int total_elems, int nparts) {
    __shared__ double sred[256];
    double s = 0.0;
    for (int i = threadIdx.x; i < nparts; i += 256) s += g_loss_part[i];
    sred[threadIdx.x] = s;
    __syncthreads();
    for (int off = 128; off; off >>= 1) {
        if (threadIdx.x < off) sred[threadIdx.x] += sred[threadIdx.x + off];
        __syncthreads();
    }
    if (threadIdx.x == 0) {
        float v = (float)(sred[0] / (double)total_elems);
        // vq_loss = codebook_loss + 0.25 * commitment_loss (identical values)
        *out_loss = __fadd_rn(v, __fmul_rn(0.25f, v));
    }
}

// --------------------------------- launch --------------------------------
extern "C" void kernel_launch(void* const* d_in, const int* in_sizes, int n_in,
                              void* d_out, int out_size) {
    const float* ze = (const float*)d_in[0];
    const float* cb = (const float*)d_in[1];
    float* out = (float*)d_out;

    const int N = in_sizes[0] / D_DIM;  // 8192
    const int K = in_sizes[1] / D_DIM;  // 8192

    cudaFuncSetAttribute(mma_phase1,
                         cudaFuncAttributeMaxDynamicSharedMemorySize, 98304);

    split_kernel<<<(N + K) / 8, 256>>>(ze, cb, N, K);

    dim3 g(N / 128, K / 256);
    mma_phase1<<<g, 256, 98304>>>();

    phase2_kernel<<<N / 8, 256>>>(ze, cb, out, out + (size_t)N * D_DIM);

    loss_final_kernel<<<1, 256>>>(out + (size_t)N * D_DIM + N,
                                  N * D_DIM, N / 8);
}

// round 15
// speedup vs baseline: 1.1037x; 1.1037x over previous
#include <cuda_runtime.h>
#include <cuda_bf16.h>
#include <stdint.h>

#define D_DIM 256
#define NROWS 8192
#define KCODES 8192
#define NTILES 64        // KCODES / 128 column tiles
#define CAP 96
#define MARGIN 2e-4f
#define LOSS_BLOCKS 1024

// ---------------- device scratch (no allocations allowed) ----------------
__device__ float g_x2[NROWS];
__device__ float g_c2[KCODES];
__device__ unsigned long long g_part[NROWS * NTILES];
__device__ double g_loss_part[LOSS_BLOCKS];
__device__ __nv_bfloat16 g_ab[NROWS * D_DIM];   // z_e rounded to bf16
__device__ __nv_bfloat16 g_bb[KCODES * D_DIM];  // codebook rounded to bf16
__device__ int g_ccnt[NROWS];
__device__ unsigned long long g_cand[NROWS * CAP];

// ------------------------------ helpers ----------------------------------
__device__ __forceinline__ uint32_t smem_u32(const void* p) {
    uint32_t a;
    asm("{ .reg .u64 t; cvta.to.shared.u64 t, %1; cvt.u32.u64 %0, t; }"
        : "=r"(a) : "l"(p));
    return a;
}
__device__ __forceinline__ void cpa16(uint32_t d, const void* s) {
    asm volatile("cp.async.cg.shared.global [%0], [%1], 16;"
                 :: "r"(d), "l"(s) : "memory");
}
__device__ __forceinline__ void ldsm4(uint32_t* r, uint32_t a) {
    asm volatile("ldmatrix.sync.aligned.m8n8.x4.shared.b16 {%0,%1,%2,%3}, [%4];"
                 : "=r"(r[0]), "=r"(r[1]), "=r"(r[2]), "=r"(r[3]) : "r"(a));
}
__device__ __forceinline__ void mma16816(float* d, const uint32_t* a,
                                         const uint32_t* b) {
    asm volatile(
        "mma.sync.aligned.m16n8k16.row.col.f32.bf16.bf16.f32 "
        "{%0,%1,%2,%3}, {%4,%5,%6,%7}, {%8,%9}, {%0,%1,%2,%3};"
        : "+f"(d[0]), "+f"(d[1]), "+f"(d[2]), "+f"(d[3])
        : "r"(a[0]), "r"(a[1]), "r"(a[2]), "r"(a[3]), "r"(b[0]), "r"(b[1]));
}
#define SW(o) ((uint32_t)(o) ^ (((uint32_t)(o) >> 3) & 0x70u))

// ------------- kernel 1: norms (exact R2 order) + bf16 copies ------------
__global__ void split_kernel(const float* __restrict__ ze,
                             const float* __restrict__ cb, int N, int K) {
    int gtid = blockIdx.x * blockDim.x + threadIdx.x;
    if (gtid < NROWS) g_ccnt[gtid] = 0;  // reset candidate counters each call
    int warp = gtid >> 5;
    int lane = threadIdx.x & 31;
    if (warp >= N + K) return;
    const float* src;
    float* dst;
    int row;
    bool is_code = (warp < K);
    if (is_code) { src = cb; dst = g_c2; row = warp; }
    else         { src = ze; dst = g_x2; row = warp - K; }
    const float* p = src + (size_t)row * D_DIM;
    float acc = 0.0f;
#pragma unroll
    for (int i = 0; i < D_DIM / 32; ++i) {
        float v = p[lane + 32 * i];
        acc = __fadd_rn(acc, __fmul_rn(v, v));
        __nv_bfloat16 h = __float2bfloat16(v);
        size_t off = (size_t)row * D_DIM + lane + 32 * i;
        if (is_code) g_bb[off] = h; else g_ab[off] = h;
    }
#pragma unroll
    for (int off = 16; off; off >>= 1)
        acc = __fadd_rn(acc, __shfl_down_sync(0xffffffffu, acc, off));
    if (lane == 0) dst[row] = acc;
}

// ------ kernel 2: bf16 mma.sync GEMM + tile-min + margin candidates ------
// grid (64, 64): 128x128 tiles. 256 threads = 8 warps (2 m x 4 n), warp 64x32.
// 3-stage cp.async pipeline, all 3 stages filled in the prologue.
// Waits 2,1,1,0: group ch is provably complete before stage ch%3 is read.
__global__ __launch_bounds__(256, 2) void mma_phase1() {
    extern __shared__ char dsm[];  // 96KB: 3 stages x (A 16KB + B 16KB)
    __shared__ unsigned long long red[2][64][4];
    __shared__ unsigned long long s_minkey[128];
    __shared__ float s_min[128];
    __shared__ float s_c2[128];
    __shared__ float s_x2[128];

    const int tid = threadIdx.x;
    const int wid = tid >> 5, lane = tid & 31;
    const int mw = wid >> 2, nw = wid & 3;
    const int row0 = blockIdx.x * 128, col0 = blockIdx.y * 128;
    const uint32_t sb = smem_u32(dsm);

    if (tid < 128) {
        s_c2[tid] = g_c2[col0 + tid];
        s_x2[tid] = g_x2[row0 + tid];
    }

    float acc[4][4][4];
#pragma unroll
    for (int i = 0; i < 4; ++i)
#pragma unroll
        for (int j = 0; j < 4; ++j)
#pragma unroll
            for (int c = 0; c < 4; ++c) acc[i][j][c] = 0.0f;

    // ---- staging: chunk ch (k = ch*64 .. +63) into stage ch%3 ----
    auto issue = [&](int ch) {
        uint32_t ab = sb + (uint32_t)(ch % 3) * 32768u;
        uint32_t bb = ab + 16384u;
        const __nv_bfloat16* ga = g_ab + (size_t)row0 * D_DIM + ch * 64;
        const __nv_bfloat16* gb = g_bb + (size_t)col0 * D_DIM + ch * 64;
#pragma unroll
        for (int t = 0; t < 4; ++t) {
            int lin = tid + t * 256;      // 0..1023
            int r = lin >> 3, gi = lin & 7;
            uint32_t off = SW(r * 128 + gi * 16);
            cpa16(ab + off, ga + (size_t)r * D_DIM + gi * 8);
            cpa16(bb + off, gb + (size_t)r * D_DIM + gi * 8);
        }
        asm volatile("cp.async.commit_group;" ::: "memory");
    };

    issue(0);
    issue(1);
    issue(2);
#pragma unroll
    for (int ch = 0; ch < 4; ++ch) {
        // group ch complete before use: ch0 ≤2 pending, ch1/ch2 ≤1, ch3 0
        if (ch == 0)      asm volatile("cp.async.wait_group 2;" ::: "memory");
        else if (ch < 3)  asm volatile("cp.async.wait_group 1;" ::: "memory");
        else              asm volatile("cp.async.wait_group 0;" ::: "memory");
        __syncthreads();
        if (ch == 1) issue(3);  // stage 0 free: chunk-0 reads fenced by sync
        uint32_t ab = sb + (uint32_t)(ch % 3) * 32768u;
        uint32_t bb = ab + 16384u;
#pragma unroll
        for (int ks = 0; ks < 4; ++ks) {
            uint32_t afr[4][4], bfr[4][2];
#pragma unroll
            for (int i = 0; i < 4; ++i) {
                int r = mw * 64 + i * 16 + (lane & 15);
                uint32_t off = SW(r * 128 + (ks * 16 + (lane >> 4) * 8) * 2);
                ldsm4(afr[i], ab + off);
            }
#pragma unroll
            for (int j2 = 0; j2 < 2; ++j2) {
                // non-trans: smem B tile is [n][k]; fragment (n=l>>2, k=2(l%4))
                int n = nw * 32 + j2 * 16 + (lane & 7) + ((lane >> 4) & 1) * 8;
                uint32_t off = SW(n * 128 + (ks * 16 + ((lane >> 3) & 1) * 8) * 2);
                uint32_t t4[4];
                ldsm4(t4, bb + off);
                bfr[j2 * 2 + 0][0] = t4[0]; bfr[j2 * 2 + 0][1] = t4[1];
                bfr[j2 * 2 + 1][0] = t4[2]; bfr[j2 * 2 + 1][1] = t4[3];
            }
#pragma unroll
            for (int i = 0; i < 4; ++i)
#pragma unroll
                for (int j = 0; j < 4; ++j) mma16816(acc[i][j], afr[i], bfr[j]);
        }
    }

    // ---- epilogue pass 1: float-domain per-thread argmin (strict <,
    //      ascending idx per thread -> first-min tie-break preserved) ----
    unsigned long long klo[4], khi[4];
#pragma unroll
    for (int i = 0; i < 4; ++i) {
        int rlo = mw * 64 + i * 16 + (lane >> 2);
        float x2lo = s_x2[rlo], x2hi = s_x2[rlo + 8];
        float dlo = 3.4e38f, dhi = 3.4e38f;
        int ilo = 0, ihi = 0;
#pragma unroll
        for (int j = 0; j < 4; ++j) {
            int c0 = nw * 32 + j * 8 + (lane & 3) * 2;
#pragma unroll
            for (int c = 0; c < 2; ++c) {
                float d = __fadd_rn(
                    __fsub_rn(x2lo, __fmul_rn(2.0f, acc[i][j][c])), s_c2[c0 + c]);
                if (d < dlo) { dlo = d; ilo = col0 + c0 + c; }
                d = __fadd_rn(
                    __fsub_rn(x2hi, __fmul_rn(2.0f, acc[i][j][2 + c])), s_c2[c0 + c]);
                if (d < dhi) { dhi = d; ihi = col0 + c0 + c; }
            }
        }
        klo[i] = ((unsigned long long)__float_as_uint(dlo) << 32) | (unsigned)ilo;
        khi[i] = ((unsigned long long)__float_as_uint(dhi) << 32) | (unsigned)ihi;
    }
#pragma unroll
    for (int s = 1; s <= 2; s <<= 1)
#pragma unroll
        for (int i = 0; i < 4; ++i) {
            unsigned long long o = __shfl_xor_sync(0xffffffffu, klo[i], s);
            if (o < klo[i]) klo[i] = o;
            o = __shfl_xor_sync(0xffffffffu, khi[i], s);
            if (o < khi[i]) khi[i] = o;
        }
    if ((lane & 3) == 0)
#pragma unroll
        for (int i = 0; i < 4; ++i) {
            red[mw][i * 16 + (lane >> 2)][nw] = klo[i];
            red[mw][i * 16 + (lane >> 2) + 8][nw] = khi[i];
        }
    __syncthreads();
    if (tid < 128) {
        unsigned long long m = red[tid >> 6][tid & 63][0];
#pragma unroll
        for (int q = 1; q < 4; ++q) {
            unsigned long long k = red[tid >> 6][tid & 63][q];
            if (k < m) m = k;
        }
        g_part[(size_t)(row0 + tid) * NTILES + blockIdx.y] = m;
        s_minkey[tid] = m;
        s_min[tid] = __uint_as_float((uint32_t)(m >> 32));
    }
    __syncthreads();
    // margin sweep: collect runner-ups within MARGIN of the tile min
#pragma unroll
    for (int i = 0; i < 4; ++i) {
        int rlo = mw * 64 + i * 16 + (lane >> 2);
#pragma unroll
        for (int half = 0; half < 2; ++half) {
            int rl = rlo + half * 8;
            float x2v = s_x2[rl];
            float thr = s_min[rl] + MARGIN;
            unsigned long long mk = s_minkey[rl];
#pragma unroll
            for (int j = 0; j < 4; ++j) {
                int c0 = nw * 32 + j * 8 + (lane & 3) * 2;
#pragma unroll
                for (int c = 0; c < 2; ++c) {
                    float d = __fadd_rn(
                        __fsub_rn(x2v, __fmul_rn(2.0f, acc[i][j][half * 2 + c])),
                        s_c2[c0 + c]);
                    if (d <= thr) {
                        unsigned long long k =
                            ((unsigned long long)__float_as_uint(d) << 32) |
                            (unsigned)(col0 + c0 + c);
                        if (k != mk) {
                            int grow = row0 + rl;
                            int pos = atomicAdd(&g_ccnt[grow], 1);
                            if (pos < CAP) g_cand[(size_t)grow * CAP + pos] = k;
                        }
                    }
                }
            }
        }
    }
}

// -- kernel 3: global min + exact recheck + fused z_q/index/loss output --
// 8 warps = 8 rows per block; grid N/8 = 1024 blocks.
__global__ __launch_bounds__(256) void phase2_kernel(
    const float* __restrict__ ze, const float* __restrict__ cb,
    float* __restrict__ out_zq, float* __restrict__ out_idx) {
    __shared__ int s_list[8][192];
    __shared__ int s_cnt[8];
    __shared__ double sred[256];
    const int wid = threadIdx.x >> 5, lane = threadIdx.x & 31;
    const int row = blockIdx.x * 8 + wid;

    unsigned long long k1 = g_part[(size_t)row * NTILES + lane];
    unsigned long long k2 = g_part[(size_t)row * NTILES + 32 + lane];
    unsigned long long m = k1 < k2 ? k1 : k2;
#pragma unroll
    for (int s = 16; s; s >>= 1) {
        unsigned long long o = __shfl_xor_sync(0xffffffffu, m, s);
        if (o < m) m = o;
    }
    m = __shfl_sync(0xffffffffu, m, 0);
    float thr = __uint_as_float((uint32_t)(m >> 32)) + MARGIN;

    if (lane == 0) s_cnt[wid] = 0;
    __syncwarp();
    int cnt = g_ccnt[row];
    bool ovf = cnt > CAP;
    if (!ovf) {
        // tile-min keys already in registers (k1 = tiles 0..31, k2 = 32..63)
        if (__uint_as_float((uint32_t)(k1 >> 32)) <= thr) {
            int pos = atomicAdd(&s_cnt[wid], 1);
            s_list[wid][pos] = (int)(k1 & 0xffffffffu);
        }
        if (__uint_as_float((uint32_t)(k2 >> 32)) <= thr) {
            int pos = atomicAdd(&s_cnt[wid], 1);
            s_list[wid][pos] = (int)(k2 & 0xffffffffu);
        }
        for (int e = lane; e < cnt; e += 32) {
            unsigned long long k = g_cand[(size_t)row * CAP + e];
            if (__uint_as_float((uint32_t)(k >> 32)) <= thr) {
                int pos = atomicAdd(&s_cnt[wid], 1);
                s_list[wid][pos] = (int)(k & 0xffffffffu);
            }
        }
    }
    __syncwarp();
    int M = ovf ? KCODES : s_cnt[wid];

    const float* zp = ze + (size_t)row * D_DIM;
    float x2v = g_x2[row];
    unsigned long long best = ~0ull;
    for (int c = lane; c < M; c += 32) {
        int code = ovf ? c : s_list[wid][c];
        const float* cp = cb + (size_t)code * D_DIM;
        float a = 0.0f;  // exact serial fp32 chain (matches verified R2 values)
#pragma unroll 8
        for (int k = 0; k < D_DIM; ++k) a = fmaf(zp[k], cp[k], a);
        float d = __fadd_rn(__fsub_rn(x2v, __fmul_rn(2.0f, a)), g_c2[code]);
        unsigned long long key =
            ((unsigned long long)__float_as_uint(d) << 32) | (unsigned)code;
        if (key < best) best = key;
    }
#pragma unroll
    for (int s = 16; s; s >>= 1) {
        unsigned long long o = __shfl_xor_sync(0xffffffffu, best, s);
        if (o < best) best = o;
    }
    int idx = (int)(best & 0xffffffffu);   // all lanes agree after butterfly
    if (lane == 0) out_idx[row] = (float)idx;

    // fused gather: z_q_st row + loss partial (exact ops of verified gather)
    const float* cp = cb + (size_t)idx * D_DIM + lane * 8;
    const float* zq = zp + lane * 8;
    float* op = out_zq + (size_t)row * D_DIM + lane * 8;
    double s = 0.0;
#pragma unroll
    for (int e = 0; e < 8; ++e) {
        float z = zq[e], c = cp[e];
        op[e] = __fadd_rn(z, __fsub_rn(c, z));  // z + (z_q - z)
        float df = __fsub_rn(z, c);
        s += (double)__fmul_rn(df, df);
    }
    sred[threadIdx.x] = s;
    __syncthreads();
    for (int off = 128; off; off >>= 1) {
        if (threadIdx.x < off) sred[threadIdx.x] += sred[threadIdx.x + off];
        __syncthreads();
    }
    if (threadIdx.x == 0) g_loss_part[blockIdx.x] = sred[0];
}

// -------------------- kernel 4: final loss reduction ---------------------
__global__ void loss_final_kernel(float* __restrict__ out_loss,
                                  int total_elems, int nparts) {
    __shared__ double sred[256];
    double s = 0.0;
    for (int i = threadIdx.x; i < nparts; i += 256) s += g_loss_part[i];
    sred[threadIdx.x] = s;
    __syncthreads();
    for (int off = 128; off; off >>= 1) {
        if (threadIdx.x < off) sred[threadIdx.x] += sred[threadIdx.x + off];
        __syncthreads();
    }
    if (threadIdx.x == 0) {
        float v = (float)(sred[0] / (double)total_elems);
        // vq_loss = codebook_loss + 0.25 * commitment_loss (identical values)
        *out_loss = __fadd_rn(v, __fmul_rn(0.25f, v));
    }
}

// --------------------------------- launch --------------------------------
extern "C" void kernel_launch(void* const* d_in, const int* in_sizes, int n_in,
                              void* d_out, int out_size) {
    const float* ze = (const float*)d_in[0];
    const float* cb = (const float*)d_in[1];
    float* out = (float*)d_out;

    const int N = in_sizes[0] / D_DIM;  // 8192
    const int K = in_sizes[1] / D_DIM;  // 8192

    cudaFuncSetAttribute(mma_phase1,
                         cudaFuncAttributeMaxDynamicSharedMemorySize, 98304);

    split_kernel<<<(N + K) / 8, 256>>>(ze, cb, N, K);

    dim3 g(N / 128, K / 128);
    mma_phase1<<<g, 256, 98304>>>();

    phase2_kernel<<<N / 8, 256>>>(ze, cb, out, out + (size_t)N * D_DIM);

    loss_final_kernel<<<1, 256>>>(out + (size_t)N * D_DIM + N,
                                  N * D_DIM, N / 8);
}

// round 16
// speedup vs baseline: 1.1138x; 1.0092x over previous
#include <cuda_runtime.h>
#include <cuda_bf16.h>
#include <stdint.h>

#define D_DIM 256
#define NROWS 8192
#define KCODES 8192
#define NTILES 64        // KCODES / 128 column tiles
#define CAP 96
#define MARGIN 2e-4f
#define LOSS_BLOCKS 1024

// ---------------- device scratch (no allocations allowed) ----------------
__device__ float g_x2[NROWS];
__device__ float g_c2[KCODES];
__device__ unsigned long long g_part[NROWS * NTILES];
__device__ double g_loss_part[LOSS_BLOCKS];
__device__ __nv_bfloat16 g_ab[NROWS * D_DIM];   // z_e rounded to bf16
__device__ __nv_bfloat16 g_bb[KCODES * D_DIM];  // codebook rounded to bf16
__device__ int g_ccnt[NROWS];
__device__ unsigned long long g_cand[NROWS * CAP];

// ------------------------------ helpers ----------------------------------
__device__ __forceinline__ uint32_t smem_u32(const void* p) {
    uint32_t a;
    asm("{ .reg .u64 t; cvta.to.shared.u64 t, %1; cvt.u32.u64 %0, t; }"
        : "=r"(a) : "l"(p));
    return a;
}
__device__ __forceinline__ void cpa16(uint32_t d, const void* s) {
    asm volatile("cp.async.cg.shared.global [%0], [%1], 16;"
                 :: "r"(d), "l"(s) : "memory");
}
__device__ __forceinline__ void ldsm4(uint32_t* r, uint32_t a) {
    asm volatile("ldmatrix.sync.aligned.m8n8.x4.shared.b16 {%0,%1,%2,%3}, [%4];"
                 : "=r"(r[0]), "=r"(r[1]), "=r"(r[2]), "=r"(r[3]) : "r"(a));
}
__device__ __forceinline__ void mma16816(float* d, const uint32_t* a,
                                         const uint32_t* b) {
    asm volatile(
        "mma.sync.aligned.m16n8k16.row.col.f32.bf16.bf16.f32 "
        "{%0,%1,%2,%3}, {%4,%5,%6,%7}, {%8,%9}, {%0,%1,%2,%3};"
        : "+f"(d[0]), "+f"(d[1]), "+f"(d[2]), "+f"(d[3])
        : "r"(a[0]), "r"(a[1]), "r"(a[2]), "r"(a[3]), "r"(b[0]), "r"(b[1]));
}
#define SW(o) ((uint32_t)(o) ^ (((uint32_t)(o) >> 3) & 0x70u))

// ------------- kernel 1: norms (exact R2 order) + bf16 copies ------------
__global__ void split_kernel(const float* __restrict__ ze,
                             const float* __restrict__ cb, int N, int K) {
    int gtid = blockIdx.x * blockDim.x + threadIdx.x;
    if (gtid < NROWS) g_ccnt[gtid] = 0;  // reset candidate counters each call
    int warp = gtid >> 5;
    int lane = threadIdx.x & 31;
    if (warp >= N + K) return;
    const float* src;
    float* dst;
    int row;
    bool is_code = (warp < K);
    if (is_code) { src = cb; dst = g_c2; row = warp; }
    else         { src = ze; dst = g_x2; row = warp - K; }
    const float* p = src + (size_t)row * D_DIM;
    float acc = 0.0f;
#pragma unroll
    for (int i = 0; i < D_DIM / 32; ++i) {
        float v = p[lane + 32 * i];
        acc = __fadd_rn(acc, __fmul_rn(v, v));
        __nv_bfloat16 h = __float2bfloat16(v);
        size_t off = (size_t)row * D_DIM + lane + 32 * i;
        if (is_code) g_bb[off] = h; else g_ab[off] = h;
    }
#pragma unroll
    for (int off = 16; off; off >>= 1)
        acc = __fadd_rn(acc, __shfl_down_sync(0xffffffffu, acc, off));
    if (lane == 0) dst[row] = acc;
}

// ------ kernel 2: bf16 mma.sync GEMM + tile-min + margin candidates ------
// grid (64, 64): 128x128 tiles. 256 threads = 8 warps (2 m x 4 n), warp 64x32.
// 3-stage cp.async pipeline, all 3 stages filled in the prologue.
// Waits 2,1,1,0: group ch is provably complete before stage ch%3 is read.
__global__ __launch_bounds__(256, 2) void mma_phase1() {
    cudaGridDependencySynchronize();  // PDL: wait for split_kernel grid
    extern __shared__ char dsm[];  // 96KB: 3 stages x (A 16KB + B 16KB)
    __shared__ unsigned long long red[2][64][4];
    __shared__ unsigned long long s_minkey[128];
    __shared__ float s_min[128];
    __shared__ float s_c2[128];
    __shared__ float s_x2[128];

    const int tid = threadIdx.x;
    const int wid = tid >> 5, lane = tid & 31;
    const int mw = wid >> 2, nw = wid & 3;
    const int row0 = blockIdx.x * 128, col0 = blockIdx.y * 128;
    const uint32_t sb = smem_u32(dsm);

    if (tid < 128) {
        s_c2[tid] = g_c2[col0 + tid];
        s_x2[tid] = g_x2[row0 + tid];
    }

    float acc[4][4][4];
#pragma unroll
    for (int i = 0; i < 4; ++i)
#pragma unroll
        for (int j = 0; j < 4; ++j)
#pragma unroll
            for (int c = 0; c < 4; ++c) acc[i][j][c] = 0.0f;

    // ---- staging: chunk ch (k = ch*64 .. +63) into stage ch%3 ----
    auto issue = [&](int ch) {
        uint32_t ab = sb + (uint32_t)(ch % 3) * 32768u;
        uint32_t bb = ab + 16384u;
        const __nv_bfloat16* ga = g_ab + (size_t)row0 * D_DIM + ch * 64;
        const __nv_bfloat16* gb = g_bb + (size_t)col0 * D_DIM + ch * 64;
#pragma unroll
        for (int t = 0; t < 4; ++t) {
            int lin = tid + t * 256;      // 0..1023
            int r = lin >> 3, gi = lin & 7;
            uint32_t off = SW(r * 128 + gi * 16);
            cpa16(ab + off, ga + (size_t)r * D_DIM + gi * 8);
            cpa16(bb + off, gb + (size_t)r * D_DIM + gi * 8);
        }
        asm volatile("cp.async.commit_group;" ::: "memory");
    };

    issue(0);
    issue(1);
    issue(2);
#pragma unroll
    for (int ch = 0; ch < 4; ++ch) {
        // group ch complete before use: ch0 ≤2 pending, ch1/ch2 ≤1, ch3 0
        if (ch == 0)      asm volatile("cp.async.wait_group 2;" ::: "memory");
        else if (ch < 3)  asm volatile("cp.async.wait_group 1;" ::: "memory");
        else              asm volatile("cp.async.wait_group 0;" ::: "memory");
        __syncthreads();
        if (ch == 1) issue(3);  // stage 0 free: chunk-0 reads fenced by sync
        uint32_t ab = sb + (uint32_t)(ch % 3) * 32768u;
        uint32_t bb = ab + 16384u;
#pragma unroll
        for (int ks = 0; ks < 4; ++ks) {
            uint32_t afr[4][4], bfr[4][2];
#pragma unroll
            for (int i = 0; i < 4; ++i) {
                int r = mw * 64 + i * 16 + (lane & 15);
                uint32_t off = SW(r * 128 + (ks * 16 + (lane >> 4) * 8) * 2);
                ldsm4(afr[i], ab + off);
            }
#pragma unroll
            for (int j2 = 0; j2 < 2; ++j2) {
                // non-trans: smem B tile is [n][k]; fragment (n=l>>2, k=2(l%4))
                int n = nw * 32 + j2 * 16 + (lane & 7) + ((lane >> 4) & 1) * 8;
                uint32_t off = SW(n * 128 + (ks * 16 + ((lane >> 3) & 1) * 8) * 2);
                uint32_t t4[4];
                ldsm4(t4, bb + off);
                bfr[j2 * 2 + 0][0] = t4[0]; bfr[j2 * 2 + 0][1] = t4[1];
                bfr[j2 * 2 + 1][0] = t4[2]; bfr[j2 * 2 + 1][1] = t4[3];
            }
#pragma unroll
            for (int i = 0; i < 4; ++i)
#pragma unroll
                for (int j = 0; j < 4; ++j) mma16816(acc[i][j], afr[i], bfr[j]);
        }
    }

    // ---- epilogue pass 1: float-domain per-thread argmin (strict <,
    //      ascending idx per thread -> first-min tie-break preserved) ----
    unsigned long long klo[4], khi[4];
#pragma unroll
    for (int i = 0; i < 4; ++i) {
        int rlo = mw * 64 + i * 16 + (lane >> 2);
        float x2lo = s_x2[rlo], x2hi = s_x2[rlo + 8];
        float dlo = 3.4e38f, dhi = 3.4e38f;
        int ilo = 0, ihi = 0;
#pragma unroll
        for (int j = 0; j < 4; ++j) {
            int c0 = nw * 32 + j * 8 + (lane & 3) * 2;
#pragma unroll
            for (int c = 0; c < 2; ++c) {
                float d = __fadd_rn(
                    __fsub_rn(x2lo, __fmul_rn(2.0f, acc[i][j][c])), s_c2[c0 + c]);
                if (d < dlo) { dlo = d; ilo = col0 + c0 + c; }
                d = __fadd_rn(
                    __fsub_rn(x2hi, __fmul_rn(2.0f, acc[i][j][2 + c])), s_c2[c0 + c]);
                if (d < dhi) { dhi = d; ihi = col0 + c0 + c; }
            }
        }
        klo[i] = ((unsigned long long)__float_as_uint(dlo) << 32) | (unsigned)ilo;
        khi[i] = ((unsigned long long)__float_as_uint(dhi) << 32) | (unsigned)ihi;
    }
#pragma unroll
    for (int s = 1; s <= 2; s <<= 1)
#pragma unroll
        for (int i = 0; i < 4; ++i) {
            unsigned long long o = __shfl_xor_sync(0xffffffffu, klo[i], s);
            if (o < klo[i]) klo[i] = o;
            o = __shfl_xor_sync(0xffffffffu, khi[i], s);
            if (o < khi[i]) khi[i] = o;
        }
    if ((lane & 3) == 0)
#pragma unroll
        for (int i = 0; i < 4; ++i) {
            red[mw][i * 16 + (lane >> 2)][nw] = klo[i];
            red[mw][i * 16 + (lane >> 2) + 8][nw] = khi[i];
        }
    __syncthreads();
    if (tid < 128) {
        unsigned long long m = red[tid >> 6][tid & 63][0];
#pragma unroll
        for (int q = 1; q < 4; ++q) {
            unsigned long long k = red[tid >> 6][tid & 63][q];
            if (k < m) m = k;
        }
        g_part[(size_t)(row0 + tid) * NTILES + blockIdx.y] = m;
        s_minkey[tid] = m;
        s_min[tid] = __uint_as_float((uint32_t)(m >> 32));
    }
    __syncthreads();
    // margin sweep: collect runner-ups within MARGIN of the tile min
#pragma unroll
    for (int i = 0; i < 4; ++i) {
        int rlo = mw * 64 + i * 16 + (lane >> 2);
#pragma unroll
        for (int half = 0; half < 2; ++half) {
            int rl = rlo + half * 8;
            float x2v = s_x2[rl];
            float thr = s_min[rl] + MARGIN;
            unsigned long long mk = s_minkey[rl];
#pragma unroll
            for (int j = 0; j < 4; ++j) {
                int c0 = nw * 32 + j * 8 + (lane & 3) * 2;
#pragma unroll
                for (int c = 0; c < 2; ++c) {
                    float d = __fadd_rn(
                        __fsub_rn(x2v, __fmul_rn(2.0f, acc[i][j][half * 2 + c])),
                        s_c2[c0 + c]);
                    if (d <= thr) {
                        unsigned long long k =
                            ((unsigned long long)__float_as_uint(d) << 32) |
                            (unsigned)(col0 + c0 + c);
                        if (k != mk) {
                            int grow = row0 + rl;
                            int pos = atomicAdd(&g_ccnt[grow], 1);
                            if (pos < CAP) g_cand[(size_t)grow * CAP + pos] = k;
                        }
                    }
                }
            }
        }
    }
}

// -- kernel 3: global min + exact recheck + fused z_q/index/loss output --
// 8 warps = 8 rows per block; grid N/8 = 1024 blocks.
__global__ __launch_bounds__(256) void phase2_kernel(
    const float* __restrict__ ze, const float* __restrict__ cb,
    float* __restrict__ out_zq, float* __restrict__ out_idx) {
    cudaGridDependencySynchronize();  // PDL: wait for mma_phase1 grid
    __shared__ int s_list[8][192];
    __shared__ int s_cnt[8];
    __shared__ double sred[256];
    const int wid = threadIdx.x >> 5, lane = threadIdx.x & 31;
    const int row = blockIdx.x * 8 + wid;

    unsigned long long k1 = g_part[(size_t)row * NTILES + lane];
    unsigned long long k2 = g_part[(size_t)row * NTILES + 32 + lane];
    unsigned long long m = k1 < k2 ? k1 : k2;
#pragma unroll
    for (int s = 16; s; s >>= 1) {
        unsigned long long o = __shfl_xor_sync(0xffffffffu, m, s);
        if (o < m) m = o;
    }
    m = __shfl_sync(0xffffffffu, m, 0);
    float thr = __uint_as_float((uint32_t)(m >> 32)) + MARGIN;

    if (lane == 0) s_cnt[wid] = 0;
    __syncwarp();
    int cnt = g_ccnt[row];
    bool ovf = cnt > CAP;
    if (!ovf) {
        // tile-min keys already in registers (k1 = tiles 0..31, k2 = 32..63)
        if (__uint_as_float((uint32_t)(k1 >> 32)) <= thr) {
            int pos = atomicAdd(&s_cnt[wid], 1);
            s_list[wid][pos] = (int)(k1 & 0xffffffffu);
        }
        if (__uint_as_float((uint32_t)(k2 >> 32)) <= thr) {
            int pos = atomicAdd(&s_cnt[wid], 1);
            s_list[wid][pos] = (int)(k2 & 0xffffffffu);
        }
        for (int e = lane; e < cnt; e += 32) {
            unsigned long long k = g_cand[(size_t)row * CAP + e];
            if (__uint_as_float((uint32_t)(k >> 32)) <= thr) {
                int pos = atomicAdd(&s_cnt[wid], 1);
                s_list[wid][pos] = (int)(k & 0xffffffffu);
            }
        }
    }
    __syncwarp();
    int M = ovf ? KCODES : s_cnt[wid];

    const float* zp = ze + (size_t)row * D_DIM;
    float x2v = g_x2[row];
    unsigned long long best = ~0ull;
    for (int c = lane; c < M; c += 32) {
        int code = ovf ? c : s_list[wid][c];
        const float* cp = cb + (size_t)code * D_DIM;
        float a = 0.0f;  // exact serial fp32 chain (matches verified R2 values)
#pragma unroll 8
        for (int k = 0; k < D_DIM; ++k) a = fmaf(zp[k], cp[k], a);
        float d = __fadd_rn(__fsub_rn(x2v, __fmul_rn(2.0f, a)), g_c2[code]);
        unsigned long long key =
            ((unsigned long long)__float_as_uint(d) << 32) | (unsigned)code;
        if (key < best) best = key;
    }
#pragma unroll
    for (int s = 16; s; s >>= 1) {
        unsigned long long o = __shfl_xor_sync(0xffffffffu, best, s);
        if (o < best) best = o;
    }
    int idx = (int)(best & 0xffffffffu);   // all lanes agree after butterfly
    if (lane == 0) out_idx[row] = (float)idx;

    // fused gather: z_q_st row + loss partial (exact ops of verified gather)
    const float* cp = cb + (size_t)idx * D_DIM + lane * 8;
    const float* zq = zp + lane * 8;
    float* op = out_zq + (size_t)row * D_DIM + lane * 8;
    double s = 0.0;
#pragma unroll
    for (int e = 0; e < 8; ++e) {
        float z = zq[e], c = cp[e];
        op[e] = __fadd_rn(z, __fsub_rn(c, z));  // z + (z_q - z)
        float df = __fsub_rn(z, c);
        s += (double)__fmul_rn(df, df);
    }
    sred[threadIdx.x] = s;
    __syncthreads();
    for (int off = 128; off; off >>= 1) {
        if (threadIdx.x < off) sred[threadIdx.x] += sred[threadIdx.x + off];
        __syncthreads();
    }
    if (threadIdx.x == 0) g_loss_part[blockIdx.x] = sred[0];
}

// -------------------- kernel 4: final loss reduction ---------------------
__global__ void loss_final_kernel(float* __restrict__ out_loss,
                                  int total_elems, int nparts) {
    cudaGridDependencySynchronize();  // PDL: wait for phase2 grid
    __shared__ double sred[256];
    double s = 0.0;
    for (int i = threadIdx.x; i < nparts; i += 256) s += g_loss_part[i];
    sred[threadIdx.x] = s;
    __syncthreads();
    for (int off = 128; off; off >>= 1) {
        if (threadIdx.x < off) sred[threadIdx.x] += sred[threadIdx.x + off];
        __syncthreads();
    }
    if (threadIdx.x == 0) {
        float v = (float)(sred[0] / (double)total_elems);
        // vq_loss = codebook_loss + 0.25 * commitment_loss (identical values)
        *out_loss = __fadd_rn(v, __fmul_rn(0.25f, v));
    }
}

// --------------------------------- launch --------------------------------
extern "C" void kernel_launch(void* const* d_in, const int* in_sizes, int n_in,
                              void* d_out, int out_size) {
    const float* ze = (const float*)d_in[0];
    const float* cb = (const float*)d_in[1];
    float* out = (float*)d_out;

    const int N = in_sizes[0] / D_DIM;  // 8192
    const int K = in_sizes[1] / D_DIM;  // 8192

    cudaFuncSetAttribute(mma_phase1,
                         cudaFuncAttributeMaxDynamicSharedMemorySize, 98304);

    split_kernel<<<(N + K) / 8, 256>>>(ze, cb, N, K);

    // PDL attribute: overlap dependent-kernel launch with predecessor tail
    cudaLaunchAttribute pdl[1];
    pdl[0].id = cudaLaunchAttributeProgrammaticStreamSerialization;
    pdl[0].val.programmaticStreamSerializationAllowed = 1;

    {
        cudaLaunchConfig_t cfg = {};
        cfg.gridDim = dim3(N / 128, K / 128);
        cfg.blockDim = dim3(256);
        cfg.dynamicSmemBytes = 98304;
        cfg.stream = 0;
        cfg.attrs = pdl;
        cfg.numAttrs = 1;
        cudaLaunchKernelEx(&cfg, mma_phase1);
    }
    {
        cudaLaunchConfig_t cfg = {};
        cfg.gridDim = dim3(N / 8);
        cfg.blockDim = dim3(256);
        cfg.stream = 0;
        cfg.attrs = pdl;
        cfg.numAttrs = 1;
        cudaLaunchKernelEx(&cfg, phase2_kernel, ze, cb, out,
                           out + (size_t)N * D_DIM);
    }
    {
        cudaLaunchConfig_t cfg = {};
        cfg.gridDim = dim3(1);
        cfg.blockDim = dim3(256);
        cfg.stream = 0;
        cfg.attrs = pdl;
        cfg.numAttrs = 1;
        cudaLaunchKernelEx(&cfg, loss_final_kernel,
                           out + (size_t)N * D_DIM + N, N * D_DIM, N / 8);
    }
}